// round 9
// baseline (speedup 1.0000x reference)
#include <cuda_runtime.h>

#define Np 1024
#define HW 4096
#define NBLK 1024       // stripe blocks
#define RPB  4          // rows per block (NBLK*RPB == HW)

// ---------------- scratch -------------------------------------------------
__device__ float    g_part[(size_t)NBLK * Np];   // 4 MB, BLK-MAJOR: [blk][box]
__device__ float    g_scores[Np];
__device__ float    g_scores_s[Np];
__device__ float    g_bbox_s[Np * 4];
__device__ unsigned g_iou[Np * 32];
__device__ float    g_rec_score[Np];
__device__ unsigned g_rec_sel[Np * 32];

// ---------------- K1: fused stripe scan + per-box row-interval sums --------
// 1024 blocks x 4 rows. FLOAT accumulators + __launch_bounds__(256,8) to
// guarantee 8 blocks/SM (64 warps/SM) — occupancy, not latency, was the
// suspected limiter. Partials reduced in double later (K2).
__global__ void __launch_bounds__(256, 8)
k_boxsum(const float4* __restrict__ p, const float* __restrict__ bbox) {
    __shared__ float srow[HW];
    __shared__ float swsum[8];
    int t = threadIdx.x;            // 256
    int lane = t & 31, wid = t >> 5;
    int blk = blockIdx.x;

    int bx1[4], bx2[4], by1[4], by2[4];
    float acc[4] = {0.f, 0.f, 0.f, 0.f};
#pragma unroll
    for (int k = 0; k < 4; k++) {
        int b = t + k * 256;
        float4 bb = reinterpret_cast<const float4*>(bbox)[b];
        bx1[k] = min(max((int)floorf(bb.x), 0), HW);
        by1[k] = min(max((int)floorf(bb.y), 0), HW);
        bx2[k] = min(max((int)floorf(bb.z), 0), HW);
        by2[k] = min(max((int)floorf(bb.w), 0), HW);
    }

    int y0 = blk * RPB;
#pragma unroll
    for (int r = 0; r < RPB; r++) {
        int y = y0 + r;
        const float4* pr = p + (size_t)y * (HW / 4);
        float4 v0 = pr[t * 4 + 0], v1 = pr[t * 4 + 1];
        float4 v2 = pr[t * 4 + 2], v3 = pr[t * 4 + 3];
        // local inclusive scan of 16 elements
        v0.y += v0.x; v0.z += v0.y; v0.w += v0.z;
        v1.x += v0.w; v1.y += v1.x; v1.z += v1.y; v1.w += v1.z;
        v2.x += v1.w; v2.y += v2.x; v2.z += v2.y; v2.w += v2.z;
        v3.x += v2.w; v3.y += v3.x; v3.z += v3.y; v3.w += v3.z;
        float tot = v3.w;
        // warp inclusive scan of per-thread totals
        float ts = tot;
#pragma unroll
        for (int o = 1; o < 32; o <<= 1) {
            float u = __shfl_up_sync(0xffffffffu, ts, o);
            if (lane >= o) ts += u;
        }
        if (lane == 31) swsum[wid] = ts;
        __syncthreads();
        float w = 0.f;
#pragma unroll
        for (int q = 0; q < 8; q++)
            if (q < wid) w += swsum[q];
        float excl = w + (ts - tot);
        v0.x += excl; v0.y += excl; v0.z += excl; v0.w += excl;
        v1.x += excl; v1.y += excl; v1.z += excl; v1.w += excl;
        v2.x += excl; v2.y += excl; v2.z += excl; v2.w += excl;
        v3.x += excl; v3.y += excl; v3.z += excl; v3.w += excl;
        float4* sr4 = reinterpret_cast<float4*>(srow);
        sr4[t * 4 + 0] = v0; sr4[t * 4 + 1] = v1;
        sr4[t * 4 + 2] = v2; sr4[t * 4 + 3] = v3;
        __syncthreads();
#pragma unroll
        for (int k = 0; k < 4; k++) {
            if (y >= by1[k] && y < by2[k]) {
                float right = (bx2[k] > 0) ? srow[bx2[k] - 1] : 0.f;
                float left  = (bx1[k] > 0) ? srow[bx1[k] - 1] : 0.f;
                acc[k] += (right - left);
            }
        }
        __syncthreads();
    }
#pragma unroll
    for (int k = 0; k < 4; k++) {
        int b = t + k * 256;
        g_part[(size_t)blk * Np + b] = acc[k];   // coalesced
    }
}

// ---------------- K2: transposed reduce of partials -> combined score ------
__global__ void k_boxscore(const float* __restrict__ bbox,
                           const float* __restrict__ obj) {
    __shared__ double sw[8][8];
    int t = threadIdx.x;            // 256
    int lane = t & 31, wid = t >> 5;
    int b0 = blockIdx.x * 8;
    int boxo = lane & 7;
    int blko = lane >> 3;
    double acc = 0.0;
    int base = wid * (NBLK / 8);
#pragma unroll 8
    for (int it = 0; it < (NBLK / 8) / 4; it++) {
        int blk = base + it * 4 + blko;
        acc += (double)g_part[(size_t)blk * Np + b0 + boxo];
    }
    acc += __shfl_down_sync(0xffffffffu, acc, 16);
    acc += __shfl_down_sync(0xffffffffu, acc, 8);
    if (lane < 8) sw[wid][lane] = acc;
    __syncthreads();
    if (t < 8) {
        double s = 0.0;
#pragma unroll
        for (int w = 0; w < 8; w++) s += sw[w][t];
        int b = b0 + t;
        float4 bb = reinterpret_cast<const float4*>(bbox)[b];
        int x1 = min(max((int)floorf(bb.x), 0), HW);
        int y1 = min(max((int)floorf(bb.y), 0), HW);
        int x2 = min(max((int)floorf(bb.z), 0), HW);
        int y2 = min(max((int)floorf(bb.w), 0), HW);
        long long cnt = (long long)(y2 - y1) * (long long)(x2 - x1);
        if (cnt < 1) cnt = 1;
        float bs = (float)(s / (double)cnt);
        g_scores[b] = 0.5f * (obj[b] + bs);
    }
}

// ---------------- K3: rank sort (desc score, ties asc index == stable) -----
__global__ void k_sort(const float* __restrict__ bbox) {
    __shared__ float ss[Np];
    int t = threadIdx.x;  // 256
    for (int k = t; k < Np; k += 256) ss[k] = g_scores[k];
    __syncthreads();
    int i    = blockIdx.x * 8 + (t >> 5);
    int lane = t & 31;
    float si = ss[i];
    int cnt = 0;
#pragma unroll
    for (int q = 0; q < 32; q++) {
        int j = q * 32 + lane;
        float sj = ss[j];
        cnt += (sj > si) || (sj == si && j < i);
    }
#pragma unroll
    for (int o = 16; o > 0; o >>= 1) cnt += __shfl_down_sync(0xffffffffu, cnt, o);
    if (lane == 0) {
        g_scores_s[cnt] = si;
        reinterpret_cast<float4*>(g_bbox_s)[cnt] =
            reinterpret_cast<const float4*>(bbox)[i];
    }
}

// ---------------- K4: IoU > 0.5 bitmask — one warp per output word ---------
__global__ void k_iou() {
    int g    = (blockIdx.x * blockDim.x + threadIdx.x) >> 5;  // 0..32767
    int lane = threadIdx.x & 31;
    int i    = g >> 5;
    int word = g & 31;
    int j    = word * 32 + lane;
    float4 a = reinterpret_cast<const float4*>(g_bbox_s)[i];
    float4 c = reinterpret_cast<const float4*>(g_bbox_s)[j];
    float aarea = (a.z - a.x) * (a.w - a.y);
    float carea = (c.z - c.x) * (c.w - c.y);
    float ix1 = fmaxf(a.x, c.x), iy1 = fmaxf(a.y, c.y);
    float ix2 = fminf(a.z, c.z), iy2 = fminf(a.w, c.w);
    float iw = fmaxf(ix2 - ix1, 0.f), ih = fmaxf(iy2 - iy1, 0.f);
    float inter = iw * ih;
    float iou = inter / (aarea + carea - inter);
    unsigned m = __ballot_sync(0xffffffffu, iou > 0.5f);
    if (lane == 0) g_iou[i * 32 + word] = m;
}

// ---------------- K5: c_wsl greedy sweep — one warp per start --------------
__global__ void k_cwsl(const int* __restrict__ counts_p) {
    int gw   = (blockIdx.x * blockDim.x + threadIdx.x) >> 5;
    int lane = threadIdx.x & 31;
    if (gw >= Np) return;
    int counts = counts_p[0];
    int i = gw;
    unsigned sel = (lane == (i >> 5)) ? (1u << (i & 31)) : 0u;
    int   size  = 1;
    float score = g_scores_s[i];
    bool  rec   = false;
    for (int j = i + 1; j < Np; j++) {
        if (size == counts) { rec = true; break; }
        unsigned row = g_iou[j * 32 + lane];
        bool overlap = __any_sync(0xffffffffu, (sel & row) != 0u);
        if (!overlap) {
            if (lane == (j >> 5)) sel |= (1u << (j & 31));
            size++;
            score += g_scores_s[j];
        }
    }
    g_rec_sel[i * 32 + lane] = sel;
    if (lane == 0) g_rec_score[i] = rec ? score : -1e30f;
}

// ---------------- K6: last-argmax over recorded scores + emit output -------
__global__ void k_final(float* __restrict__ out) {
    __shared__ float ss[Np];
    __shared__ int   si[Np];
    int t = threadIdx.x;
    ss[t] = g_rec_score[t];
    si[t] = t;
    __syncthreads();
    for (int s = Np / 2; s > 0; s >>= 1) {
        if (t < s) {
            float o = ss[t + s]; int oi = si[t + s];
            if (o > ss[t] || (o == ss[t] && oi > si[t])) { ss[t] = o; si[t] = oi; }
        }
        __syncthreads();
    }
    __shared__ int bestIdx, anyrec;
    if (t == 0) { bestIdx = si[0]; anyrec = (ss[0] > -1e29f) ? 1 : 0; }
    __syncthreads();
    unsigned bit = (g_rec_sel[bestIdx * 32 + (t >> 5)] >> (t & 31)) & 1u;
    out[t] = (anyrec && bit) ? g_scores_s[t] : 0.f;
}

// ---------------- launch ----------------------------------------------------
extern "C" void kernel_launch(void* const* d_in, const int* in_sizes, int n_in,
                              void* d_out, int out_size) {
    const float* bbox   = (const float*)d_in[0];
    const float* obj    = (const float*)d_in[1];
    const float* probs  = (const float*)d_in[2];
    const int*   counts = (const int*)d_in[3];
    float* out = (float*)d_out;

    k_boxsum<<<NBLK, 256>>>((const float4*)probs, bbox);
    k_boxscore<<<Np / 8, 256>>>(bbox, obj);
    k_sort<<<Np / 8, 256>>>(bbox);
    k_iou<<<(Np * 32 * 32) / 256, 256>>>();
    k_cwsl<<<(Np * 32) / 256, 256>>>(counts);
    k_final<<<1, Np>>>(out);
}

// round 10
// speedup vs baseline: 1.1846x; 1.1846x over previous
#include <cuda_runtime.h>

#define Np 1024
#define HW 4096
#define NBLK 1024       // stripe blocks
#define RPB  4          // rows per block (NBLK*RPB == HW)

// ---------------- scratch -------------------------------------------------
__device__ float    g_part[(size_t)NBLK * Np];   // 4 MB, BLK-MAJOR: [blk][box]
__device__ float    g_scores[Np];
__device__ float    g_scores_s[Np];
__device__ float    g_bbox_s[Np * 4];
__device__ unsigned g_iou[Np * 32];
__device__ unsigned g_rec_sel[Np * 32];
__device__ unsigned long long g_best;            // (scorebits<<32)|idx, 0 = none

// ---------------- K1: fused stripe scan + per-box row-interval sums --------
// (round-6 version verbatim: double acc, no launch_bounds, no prefetch)
__global__ void k_boxsum(const float4* __restrict__ p,
                         const float* __restrict__ bbox) {
    if (blockIdx.x == 0 && threadIdx.x == 0) g_best = 0ull;  // replay reset
    __shared__ float srow[HW];
    __shared__ float swsum[8];
    int t = threadIdx.x;            // 256
    int lane = t & 31, wid = t >> 5;
    int blk = blockIdx.x;

    int bx1[4], bx2[4], by1[4], by2[4];
    double acc[4] = {0.0, 0.0, 0.0, 0.0};
#pragma unroll
    for (int k = 0; k < 4; k++) {
        int b = t + k * 256;
        float4 bb = reinterpret_cast<const float4*>(bbox)[b];
        bx1[k] = min(max((int)floorf(bb.x), 0), HW);
        by1[k] = min(max((int)floorf(bb.y), 0), HW);
        bx2[k] = min(max((int)floorf(bb.z), 0), HW);
        by2[k] = min(max((int)floorf(bb.w), 0), HW);
    }

    int y0 = blk * RPB;
#pragma unroll
    for (int r = 0; r < RPB; r++) {
        int y = y0 + r;
        const float4* pr = p + (size_t)y * (HW / 4);
        float4 v0 = pr[t * 4 + 0], v1 = pr[t * 4 + 1];
        float4 v2 = pr[t * 4 + 2], v3 = pr[t * 4 + 3];
        v0.y += v0.x; v0.z += v0.y; v0.w += v0.z;
        v1.x += v0.w; v1.y += v1.x; v1.z += v1.y; v1.w += v1.z;
        v2.x += v1.w; v2.y += v2.x; v2.z += v2.y; v2.w += v2.z;
        v3.x += v2.w; v3.y += v3.x; v3.z += v3.y; v3.w += v3.z;
        float tot = v3.w;
        float ts = tot;
#pragma unroll
        for (int o = 1; o < 32; o <<= 1) {
            float u = __shfl_up_sync(0xffffffffu, ts, o);
            if (lane >= o) ts += u;
        }
        if (lane == 31) swsum[wid] = ts;
        __syncthreads();
        float w = 0.f;
#pragma unroll
        for (int q = 0; q < 8; q++)
            if (q < wid) w += swsum[q];
        float excl = w + (ts - tot);
        v0.x += excl; v0.y += excl; v0.z += excl; v0.w += excl;
        v1.x += excl; v1.y += excl; v1.z += excl; v1.w += excl;
        v2.x += excl; v2.y += excl; v2.z += excl; v2.w += excl;
        v3.x += excl; v3.y += excl; v3.z += excl; v3.w += excl;
        float4* sr4 = reinterpret_cast<float4*>(srow);
        sr4[t * 4 + 0] = v0; sr4[t * 4 + 1] = v1;
        sr4[t * 4 + 2] = v2; sr4[t * 4 + 3] = v3;
        __syncthreads();
#pragma unroll
        for (int k = 0; k < 4; k++) {
            if (y >= by1[k] && y < by2[k]) {
                float right = (bx2[k] > 0) ? srow[bx2[k] - 1] : 0.f;
                float left  = (bx1[k] > 0) ? srow[bx1[k] - 1] : 0.f;
                acc[k] += (double)(right - left);
            }
        }
        __syncthreads();
    }
#pragma unroll
    for (int k = 0; k < 4; k++) {
        int b = t + k * 256;
        g_part[(size_t)blk * Np + b] = (float)acc[k];   // coalesced
    }
}

// ---------------- K2: transposed reduce of partials -> combined score ------
__global__ void k_boxscore(const float* __restrict__ bbox,
                           const float* __restrict__ obj) {
    __shared__ double sw[8][8];
    int t = threadIdx.x;            // 256
    int lane = t & 31, wid = t >> 5;
    int b0 = blockIdx.x * 8;
    int boxo = lane & 7;
    int blko = lane >> 3;
    double acc = 0.0;
    int base = wid * (NBLK / 8);
#pragma unroll 8
    for (int it = 0; it < (NBLK / 8) / 4; it++) {
        int blk = base + it * 4 + blko;
        acc += (double)g_part[(size_t)blk * Np + b0 + boxo];
    }
    acc += __shfl_down_sync(0xffffffffu, acc, 16);
    acc += __shfl_down_sync(0xffffffffu, acc, 8);
    if (lane < 8) sw[wid][lane] = acc;
    __syncthreads();
    if (t < 8) {
        double s = 0.0;
#pragma unroll
        for (int w = 0; w < 8; w++) s += sw[w][t];
        int b = b0 + t;
        float4 bb = reinterpret_cast<const float4*>(bbox)[b];
        int x1 = min(max((int)floorf(bb.x), 0), HW);
        int y1 = min(max((int)floorf(bb.y), 0), HW);
        int x2 = min(max((int)floorf(bb.z), 0), HW);
        int y2 = min(max((int)floorf(bb.w), 0), HW);
        long long cnt = (long long)(y2 - y1) * (long long)(x2 - x1);
        if (cnt < 1) cnt = 1;
        float bs = (float)(s / (double)cnt);
        g_scores[b] = 0.5f * (obj[b] + bs);
    }
}

// ---------------- K3: rank sort (desc score, ties asc index == stable) -----
__global__ void k_sort(const float* __restrict__ bbox) {
    __shared__ float ss[Np];
    int t = threadIdx.x;  // 256
    for (int k = t; k < Np; k += 256) ss[k] = g_scores[k];
    __syncthreads();
    int i    = blockIdx.x * 8 + (t >> 5);
    int lane = t & 31;
    float si = ss[i];
    int cnt = 0;
#pragma unroll
    for (int q = 0; q < 32; q++) {
        int j = q * 32 + lane;
        float sj = ss[j];
        cnt += (sj > si) || (sj == si && j < i);
    }
#pragma unroll
    for (int o = 16; o > 0; o >>= 1) cnt += __shfl_down_sync(0xffffffffu, cnt, o);
    if (lane == 0) {
        g_scores_s[cnt] = si;
        reinterpret_cast<float4*>(g_bbox_s)[cnt] =
            reinterpret_cast<const float4*>(bbox)[i];
    }
}

// ---------------- K4: IoU bitmask — one warp = one word for TWO rows --------
// Shares the j-box load + carea across rows i0, i0+1; 16384 warps.
__global__ void k_iou() {
    int g    = (blockIdx.x * blockDim.x + threadIdx.x) >> 5;  // 0..16383
    int lane = threadIdx.x & 31;
    int ip   = g >> 5;            // row pair 0..511
    int word = g & 31;
    int i0   = ip * 2;
    int j    = word * 32 + lane;
    float4 c  = reinterpret_cast<const float4*>(g_bbox_s)[j];
    float4 a0 = reinterpret_cast<const float4*>(g_bbox_s)[i0];
    float4 a1 = reinterpret_cast<const float4*>(g_bbox_s)[i0 + 1];
    float carea = (c.z - c.x) * (c.w - c.y);

    float a0area = (a0.z - a0.x) * (a0.w - a0.y);
    float ix1 = fmaxf(a0.x, c.x), iy1 = fmaxf(a0.y, c.y);
    float ix2 = fminf(a0.z, c.z), iy2 = fminf(a0.w, c.w);
    float inter0 = fmaxf(ix2 - ix1, 0.f) * fmaxf(iy2 - iy1, 0.f);
    float iou0 = inter0 / (a0area + carea - inter0);
    unsigned m0 = __ballot_sync(0xffffffffu, iou0 > 0.5f);

    float a1area = (a1.z - a1.x) * (a1.w - a1.y);
    float jx1 = fmaxf(a1.x, c.x), jy1 = fmaxf(a1.y, c.y);
    float jx2 = fminf(a1.z, c.z), jy2 = fminf(a1.w, c.w);
    float inter1 = fmaxf(jx2 - jx1, 0.f) * fmaxf(jy2 - jy1, 0.f);
    float iou1 = inter1 / (a1area + carea - inter1);
    unsigned m1 = __ballot_sync(0xffffffffu, iou1 > 0.5f);

    if (lane == 0) {
        g_iou[i0 * 32 + word]       = m0;
        g_iou[(i0 + 1) * 32 + word] = m1;
    }
}

// ---------------- K5: c_wsl greedy sweep — prefetch + break-at-add ----------
// size hits counts at iter j0 -> reference records at top of iter j0+1 iff
// j0+1 <= Np-1 (round-4 verified logic). Winner via atomicMax on
// (scorebits<<32)|idx == last-argmax ('>=' update) rule.
__global__ void k_cwsl(const int* __restrict__ counts_p) {
    int gw   = (blockIdx.x * blockDim.x + threadIdx.x) >> 5;
    int lane = threadIdx.x & 31;
    if (gw >= Np) return;
    int counts = counts_p[0];
    int i = gw;
    unsigned sel = (lane == (i >> 5)) ? (1u << (i & 31)) : 0u;
    int   size  = 1;
    float score = g_scores_s[i];
    bool  rec   = false;
    if (size == counts) {
        rec = (i < Np - 1);
    } else {
        unsigned row = (i + 1 < Np) ? g_iou[(i + 1) * 32 + lane] : 0u;
        for (int j = i + 1; j < Np; j++) {
            unsigned nxt = (j + 1 < Np) ? g_iou[(j + 1) * 32 + lane] : 0u;
            bool overlap = __any_sync(0xffffffffu, (sel & row) != 0u);
            if (!overlap) {
                if (lane == (j >> 5)) sel |= (1u << (j & 31));
                size++;
                score += g_scores_s[j];
                if (size == counts) { rec = (j < Np - 1); break; }
            }
            row = nxt;
        }
    }
    g_rec_sel[i * 32 + lane] = sel;
    if (lane == 0 && rec) {
        unsigned long long key =
            ((unsigned long long)__float_as_uint(score) << 32) | (unsigned)i;
        atomicMax(&g_best, key);
    }
}

// ---------------- K6: decode winner + emit output ---------------------------
__global__ void k_final(float* __restrict__ out) {
    int t = threadIdx.x;
    unsigned long long key = g_best;
    int best = (int)(key & 0xffffffffu);
    bool any = (key != 0ull);
    unsigned bit = (g_rec_sel[best * 32 + (t >> 5)] >> (t & 31)) & 1u;
    out[t] = (any && bit) ? g_scores_s[t] : 0.f;
}

// ---------------- launch ----------------------------------------------------
extern "C" void kernel_launch(void* const* d_in, const int* in_sizes, int n_in,
                              void* d_out, int out_size) {
    const float* bbox   = (const float*)d_in[0];
    const float* obj    = (const float*)d_in[1];
    const float* probs  = (const float*)d_in[2];
    const int*   counts = (const int*)d_in[3];
    float* out = (float*)d_out;

    k_boxsum<<<NBLK, 256>>>((const float4*)probs, bbox);
    k_boxscore<<<Np / 8, 256>>>(bbox, obj);
    k_sort<<<Np / 8, 256>>>(bbox);
    k_iou<<<(Np / 2 * 32 * 32) / 256, 256>>>();
    k_cwsl<<<(Np * 32) / 256, 256>>>(counts);
    k_final<<<1, Np>>>(out);
}